// round 1
// baseline (speedup 1.0000x reference)
#include <cuda_runtime.h>

// Problem constants (fixed by the dataset)
#define T_LEN 4096
#define B_SZ  32
#define C_SZ  300
#define W_SZ  128
#define C4    (C_SZ / 4)     // 75 float4 per (t,b) row
#define ROW4  (B_SZ * C4)    // 2400 float4 per t-slice

// Scratch (allocation-free rule: __device__ globals)
__device__ int g_starts[B_SZ * W_SZ];
__device__ int g_total[B_SZ];
__device__ int g_pos[B_SZ * T_LEN];   // pos if t < total[b], else -1

// Kernel 1: per-sample exclusive cumsum of durations (one warp per b).
__global__ void k_scan(const int* __restrict__ dur) {
    int b = threadIdx.x >> 5;
    int l = threadIdx.x & 31;
    const int* d = dur + b * W_SZ + l * 4;
    int d0 = d[0], d1 = d[1], d2 = d[2], d3 = d[3];
    int s = d0 + d1 + d2 + d3;
    int incl = s;
#pragma unroll
    for (int o = 1; o < 32; o <<= 1) {
        int v = __shfl_up_sync(0xffffffffu, incl, o);
        if (l >= o) incl += v;
    }
    int base = incl - s;  // exclusive prefix of this lane's group of 4
    int* st = g_starts + b * W_SZ + l * 4;
    st[0] = base;
    st[1] = base + d0;
    st[2] = base + d0 + d1;
    st[3] = base + d0 + d1 + d2;
    int tot = __shfl_sync(0xffffffffu, incl, 31);
    if (l == 0) g_total[b] = tot;
}

// Kernel 2: per-(b,t) segment position via binary search over sorted starts.
// starts[0] == 0 always, so "largest start <= t" always exists.
__global__ void k_pos() {
    __shared__ int s_st[W_SZ];
    int b = blockIdx.x;
    if (threadIdx.x < W_SZ) s_st[threadIdx.x] = g_starts[b * W_SZ + threadIdx.x];
    __syncthreads();
    int tot = g_total[b];
    for (int t = threadIdx.x; t < T_LEN; t += blockDim.x) {
        int lo = 0, hi = W_SZ - 1;
#pragma unroll
        for (int i = 0; i < 7; i++) {      // 128 -> 1
            int mid = (lo + hi + 1) >> 1;
            if (s_st[mid] <= t) lo = mid; else hi = mid - 1;
        }
        int seg = s_st[lo];
        // pos = t - seg in [0, t] ⊂ [0, 4095] < MAX_LEN=5000, so no clip needed.
        g_pos[b * T_LEN + t] = (t < tot) ? (t - seg) : -1;
    }
}

// Kernel 3: streaming add. One block per t-slice (B*C = 2400 float4).
__global__ void __launch_bounds__(256) k_add(const float4* __restrict__ x,
                                             const float4* __restrict__ pe,
                                             float4* __restrict__ out) {
    __shared__ int s_pos[B_SZ];
    int t = blockIdx.x;
    if (threadIdx.x < B_SZ) s_pos[threadIdx.x] = g_pos[threadIdx.x * T_LEN + t];
    __syncthreads();
    const float4* xrow = x + (size_t)t * ROW4;
    float4*       orow = out + (size_t)t * ROW4;
    for (int j = threadIdx.x; j < ROW4; j += 256) {
        int b  = j / C4;          // constant divide -> mul/shift
        int c4 = j - b * C4;
        float4 v = xrow[j];
        int p = s_pos[b];
        if (p >= 0) {
            float4 pv = __ldg(pe + p * C4 + c4);  // 6 MB table: L2-resident
            v.x += pv.x; v.y += pv.y; v.z += pv.z; v.w += pv.w;
        }
        orow[j] = v;
    }
}

extern "C" void kernel_launch(void* const* d_in, const int* in_sizes, int n_in,
                              void* d_out, int out_size) {
    const float* x  = (const float*)d_in[0];
    const float* pe = (const float*)d_in[1];
    const int*   du = (const int*)d_in[2];
    // d_in[3] = train flag, unused by the reference math.
    k_scan<<<1, 32 * B_SZ>>>(du);
    k_pos<<<B_SZ, 256>>>();
    k_add<<<T_LEN, 256>>>((const float4*)x, (const float4*)pe, (float4*)d_out);
}

// round 2
// speedup vs baseline: 1.2312x; 1.2312x over previous
#include <cuda_runtime.h>

// Problem constants (fixed by the dataset)
#define T_LEN 4096
#define B_SZ  32
#define C_SZ  300
#define W_SZ  128
#define C4    (C_SZ / 4)     // 75 float4 per (t,b) row
#define ROW4  (B_SZ * C4)    // 2400 float4 per t-slice

// Fused kernel: one block per t.
// Prologue: 8 warps x 4 samples each -> s_pos[32] (segment-relative position
// or -1 if masked). Then stream the 2400-float4 (b, c) slice.
__global__ void __launch_bounds__(256) k_fused(const float4* __restrict__ x,
                                               const float4* __restrict__ pe,
                                               const int*    __restrict__ dur,
                                               float4*       __restrict__ out) {
    __shared__ int s_pos[B_SZ];
    const int t    = blockIdx.x;
    const int warp = threadIdx.x >> 5;
    const int lane = threadIdx.x & 31;

    // ---- prologue: segment position for 4 samples per warp ----
#pragma unroll
    for (int k = 0; k < 4; k++) {
        const int b = warp * 4 + k;
        // lane covers duration indices 4*lane .. 4*lane+3
        int4 d4 = *(const int4*)(dur + b * W_SZ + lane * 4);
        int s = d4.x + d4.y + d4.z + d4.w;
        int incl = s;
#pragma unroll
        for (int o = 1; o < 32; o <<= 1) {
            int v = __shfl_up_sync(0xffffffffu, incl, o);
            if (lane >= o) incl += v;
        }
        int base = incl - s;                       // exclusive prefix across lanes
        int st0 = base;
        int st1 = base + d4.x;
        int st2 = st1 + d4.y;
        int st3 = st2 + d4.z;
        int tot = __shfl_sync(0xffffffffu, incl, 31);

        // largest start <= t: starts are globally nondecreasing across lanes.
        // Owning lane = highest lane whose first start <= t (lane 0 has st0=0).
        unsigned m = __ballot_sync(0xffffffffu, st0 <= t);
        int L = 31 - __clz(m);
        int loc = st0;
        if (st1 <= t) loc = st1;
        if (st2 <= t) loc = st2;
        if (st3 <= t) loc = st3;
        int seg = __shfl_sync(0xffffffffu, loc, L);

        if (lane == 0) s_pos[b] = (t < tot) ? (t - seg) : -1;
    }
    __syncthreads();

    // ---- streaming add ----
    const float4* xrow = x + (size_t)t * ROW4;
    float4*       orow = out + (size_t)t * ROW4;
    for (int j = threadIdx.x; j < ROW4; j += 256) {
        int b  = j / C4;                 // constant divide -> mul/shift
        int c4 = j - b * C4;
        float4 v = xrow[j];
        int p = s_pos[b];
        if (p >= 0) {
            float4 pv = __ldg(pe + p * C4 + c4);   // 6 MB table: L2-resident
            v.x += pv.x; v.y += pv.y; v.z += pv.z; v.w += pv.w;
        }
        orow[j] = v;
    }
}

extern "C" void kernel_launch(void* const* d_in, const int* in_sizes, int n_in,
                              void* d_out, int out_size) {
    const float* x  = (const float*)d_in[0];
    const float* pe = (const float*)d_in[1];
    const int*   du = (const int*)d_in[2];
    // d_in[3] = train flag, unused by the reference math.
    k_fused<<<T_LEN, 256>>>((const float4*)x, (const float4*)pe, du, (float4*)d_out);
}

// round 3
// speedup vs baseline: 1.3133x; 1.0667x over previous
#include <cuda_runtime.h>

// Problem constants (fixed by the dataset)
#define T_LEN 4096
#define B_SZ  32
#define C_SZ  300
#define W_SZ  128
#define C4    (C_SZ / 4)     // 75 float4 per (t,b) row
#define ROW4  (B_SZ * C4)    // 2400 float4 per t-slice
#define NTHR  480            // 2400 = 480 * 5 exactly
#define UNROLL 5

// Fused kernel: one block per t.
// Prologue: warps 0-7, 4 samples each -> s_pos[32] (segment-relative position
// or -1 if masked). Then stream the 2400-float4 (b, c) slice with unroll 5.
__global__ void __launch_bounds__(NTHR) k_fused(const float4* __restrict__ x,
                                                const float4* __restrict__ pe,
                                                const int*    __restrict__ dur,
                                                float4*       __restrict__ out) {
    __shared__ int s_pos[B_SZ];
    const int t    = blockIdx.x;
    const int warp = threadIdx.x >> 5;
    const int lane = threadIdx.x & 31;

    // ---- prologue: segment position for 4 samples per warp (warps 0-7) ----
    if (warp < 8) {
#pragma unroll
        for (int k = 0; k < 4; k++) {
            const int b = warp * 4 + k;
            // lane covers duration indices 4*lane .. 4*lane+3
            int4 d4 = *(const int4*)(dur + b * W_SZ + lane * 4);
            int s = d4.x + d4.y + d4.z + d4.w;
            int incl = s;
#pragma unroll
            for (int o = 1; o < 32; o <<= 1) {
                int v = __shfl_up_sync(0xffffffffu, incl, o);
                if (lane >= o) incl += v;
            }
            int base = incl - s;                   // exclusive prefix across lanes
            int st0 = base;
            int st1 = base + d4.x;
            int st2 = st1 + d4.y;
            int st3 = st2 + d4.z;
            int tot = __shfl_sync(0xffffffffu, incl, 31);

            // Largest start <= t: starts are globally nondecreasing across lanes.
            unsigned m = __ballot_sync(0xffffffffu, st0 <= t);
            int L = 31 - __clz(m);
            int loc = st0;
            if (st1 <= t) loc = st1;
            if (st2 <= t) loc = st2;
            if (st3 <= t) loc = st3;
            int seg = __shfl_sync(0xffffffffu, loc, L);

            if (lane == 0) s_pos[b] = (t < tot) ? (t - seg) : -1;
        }
    }
    __syncthreads();

    // ---- streaming add: exact unroll, batched x loads for MLP ----
    const float4* xrow = x + (size_t)t * ROW4;
    float4*       orow = out + (size_t)t * ROW4;
    const int tid = threadIdx.x;

    float4 v[UNROLL];
    int    bb[UNROLL], cc[UNROLL];
#pragma unroll
    for (int i = 0; i < UNROLL; i++) {
        int j = tid + i * NTHR;
        bb[i] = j / C4;                    // constant divide -> mul/shift
        cc[i] = j - bb[i] * C4;
        v[i]  = __ldcs(xrow + j);          // streaming read (evict-first)
    }
#pragma unroll
    for (int i = 0; i < UNROLL; i++) {
        int p = s_pos[bb[i]];
        if (p >= 0) {
            float4 pv = __ldg(pe + p * C4 + cc[i]);   // 6 MB table: L2-resident
            v[i].x += pv.x; v[i].y += pv.y; v[i].z += pv.z; v[i].w += pv.w;
        }
    }
#pragma unroll
    for (int i = 0; i < UNROLL; i++) {
        __stcs(orow + tid + i * NTHR, v[i]);          // streaming write
    }
}

extern "C" void kernel_launch(void* const* d_in, const int* in_sizes, int n_in,
                              void* d_out, int out_size) {
    const float* x  = (const float*)d_in[0];
    const float* pe = (const float*)d_in[1];
    const int*   du = (const int*)d_in[2];
    // d_in[3] = train flag, unused by the reference math.
    k_fused<<<T_LEN, NTHR>>>((const float4*)x, (const float4*)pe, du, (float4*)d_out);
}

// round 4
// speedup vs baseline: 1.3280x; 1.0111x over previous
#include <cuda_runtime.h>

// Problem constants (fixed by the dataset)
#define T_LEN 4096
#define B_SZ  32
#define C_SZ  300
#define W_SZ  128
#define C4    (C_SZ / 4)     // 75 float4 per (t,b) row
#define ROW4  (B_SZ * C4)    // 2400 float4 per t-slice
#define NTHR  480            // 2400 = 480 * 5 exactly
#define UNROLL 5

// Fused kernel: one block per t.
// Order matters: the 5 streaming x-loads are issued FIRST (they don't depend
// on the segment scan), so the prologue scan + barrier latency is fully
// overlapped with DRAM misses already in flight.
__global__ void __launch_bounds__(NTHR) k_fused(const float4* __restrict__ x,
                                                const float4* __restrict__ pe,
                                                const int*    __restrict__ dur,
                                                float4*       __restrict__ out) {
    __shared__ int s_pos[B_SZ];
    const int t    = blockIdx.x;
    const int warp = threadIdx.x >> 5;
    const int lane = threadIdx.x & 31;
    const int tid  = threadIdx.x;

    // ---- issue streaming x loads immediately ----
    const float4* xrow = x + (size_t)t * ROW4;
    float4*       orow = out + (size_t)t * ROW4;

    float4 v[UNROLL];
    int    bb[UNROLL], cc[UNROLL];
#pragma unroll
    for (int i = 0; i < UNROLL; i++) {
        int j = tid + i * NTHR;
        bb[i] = j / C4;                    // constant divide -> mul/shift
        cc[i] = j - bb[i] * C4;
        v[i]  = __ldcs(xrow + j);          // streaming read (evict-first)
    }

    // ---- prologue: segment position for 4 samples per warp (warps 0-7),
    //      overlapped with the x loads above ----
    if (warp < 8) {
#pragma unroll
        for (int k = 0; k < 4; k++) {
            const int b = warp * 4 + k;
            int4 d4 = *(const int4*)(dur + b * W_SZ + lane * 4);
            int s = d4.x + d4.y + d4.z + d4.w;
            int incl = s;
#pragma unroll
            for (int o = 1; o < 32; o <<= 1) {
                int vv = __shfl_up_sync(0xffffffffu, incl, o);
                if (lane >= o) incl += vv;
            }
            int base = incl - s;                   // exclusive prefix across lanes
            int st0 = base;
            int st1 = base + d4.x;
            int st2 = st1 + d4.y;
            int st3 = st2 + d4.z;
            int tot = __shfl_sync(0xffffffffu, incl, 31);

            // Largest start <= t: starts are globally nondecreasing across lanes.
            unsigned m = __ballot_sync(0xffffffffu, st0 <= t);
            int L = 31 - __clz(m);
            int loc = st0;
            if (st1 <= t) loc = st1;
            if (st2 <= t) loc = st2;
            if (st3 <= t) loc = st3;
            int seg = __shfl_sync(0xffffffffu, loc, L);

            if (lane == 0) s_pos[b] = (t < tot) ? (t - seg) : -1;
        }
    }
    __syncthreads();

    // ---- pe add + streaming store ----
#pragma unroll
    for (int i = 0; i < UNROLL; i++) {
        int p = s_pos[bb[i]];
        if (p >= 0) {
            float4 pv = __ldg(pe + p * C4 + cc[i]);   // 6 MB table: L2-resident
            v[i].x += pv.x; v[i].y += pv.y; v[i].z += pv.z; v[i].w += pv.w;
        }
    }
#pragma unroll
    for (int i = 0; i < UNROLL; i++) {
        __stcs(orow + tid + i * NTHR, v[i]);          // streaming write
    }
}

extern "C" void kernel_launch(void* const* d_in, const int* in_sizes, int n_in,
                              void* d_out, int out_size) {
    const float* x  = (const float*)d_in[0];
    const float* pe = (const float*)d_in[1];
    const int*   du = (const int*)d_in[2];
    // d_in[3] = train flag, unused by the reference math.
    k_fused<<<T_LEN, NTHR>>>((const float4*)x, (const float4*)pe, du, (float4*)d_out);
}